// round 12
// baseline (speedup 1.0000x reference)
#include <cuda_runtime.h>
#include <cuda_fp16.h>
#include <cstdint>

#define D 128
#define N_MAX 50048
#define E_MAX 1600512
#define NB_MAX 64   // max scan blocks (ceil(50000/1024)=49)

// Scratch (device globals: allocation-free per harness rules)
__device__ int     g_deg[N_MAX];
__device__ int     g_rowcnt[N_MAX];
__device__ int     g_roff[N_MAX + 1];
__device__ int     g_cursor[N_MAX];
__device__ int     g_bsum[NB_MAX];
__device__ int     g_boff[NB_MAX];
__device__ int     g_adj[E_MAX];
__device__ float   g_dinv[N_MAX];
__device__ __half2 g_yh[(size_t)N_MAX * (D / 2)];  // y in fp16: halves gather L2 traffic

// ---------------------------------------------------------------------------
// 1) init: self-loop degree 1, row counters 0
__global__ void k_init(int n) {
    int i = blockIdx.x * blockDim.x + threadIdx.x;
    if (i < n) { g_deg[i] = 1; g_rowcnt[i] = 0; }
}

// 2) fused histogram: degree over col, CSR counts over row (one pass over ei)
__global__ void k_hist(const int* __restrict__ ei, int E) {
    int i = blockIdx.x * blockDim.x + threadIdx.x;
    if (i < E) {
        int r = ei[i];
        int c = ei[E + i];
        atomicAdd(&g_deg[c], 1);
        atomicAdd(&g_rowcnt[r], 1);
    }
}

// ---------------------------------------------------------------------------
// 3a) per-block exclusive scan of 1024-element chunks + block sums
__global__ __launch_bounds__(1024) void k_scan_blk(int n) {
    __shared__ int warp_sums[32];
    const int tid = threadIdx.x, lane = tid & 31, wid = tid >> 5;
    const int i = blockIdx.x * 1024 + tid;

    int v = (i < n) ? g_rowcnt[i] : 0;
    int inc = v;
#pragma unroll
    for (int o = 1; o < 32; o <<= 1) {
        int t = __shfl_up_sync(0xffffffffu, inc, o);
        if (lane >= o) inc += t;
    }
    if (lane == 31) warp_sums[wid] = inc;
    __syncthreads();
    if (wid == 0) {
        int ws = warp_sums[lane];
#pragma unroll
        for (int o = 1; o < 32; o <<= 1) {
            int t = __shfl_up_sync(0xffffffffu, ws, o);
            if (lane >= o) ws += t;
        }
        warp_sums[lane] = ws;
    }
    __syncthreads();
    int excl = ((wid == 0) ? 0 : warp_sums[wid - 1]) + inc - v;
    if (i < n) g_roff[i] = excl;
    if (tid == 0) g_bsum[blockIdx.x] = warp_sums[31];
}

// 3b) scan the block sums (nb <= 64, one 64-thread block)
__global__ void k_scan_top(int nb, int n) {
    __shared__ int ws[2];
    const int tid = threadIdx.x, lane = tid & 31, wid = tid >> 5;
    int v = (tid < nb) ? g_bsum[tid] : 0;
    int inc = v;
#pragma unroll
    for (int o = 1; o < 32; o <<= 1) {
        int t = __shfl_up_sync(0xffffffffu, inc, o);
        if (lane >= o) inc += t;
    }
    if (lane == 31) ws[wid] = inc;
    __syncthreads();
    int excl = inc - v + ((wid == 1) ? ws[0] : 0);
    if (tid < nb) g_boff[tid] = excl;
    if (tid == nb - 1) g_roff[n] = excl + v;
}

// 3c) add block offsets -> final roff/cursor; fused dinv = rsqrt(deg)
__global__ void k_scan_add(int n) {
    int i = blockIdx.x * blockDim.x + threadIdx.x;
    if (i < n) {
        int r = g_roff[i] + g_boff[i >> 10];
        g_roff[i] = r;
        g_cursor[i] = r;
        g_dinv[i] = rsqrtf((float)g_deg[i]);
    }
}

// 4) CSR fill: adj[cursor[r]++] = c  (order within a row irrelevant: sum)
__global__ void k_fill(const int* __restrict__ ei, int E) {
    int i = blockIdx.x * blockDim.x + threadIdx.x;
    if (i < E) {
        int r = ei[i];
        int c = ei[E + i];
        int pos = atomicAdd(&g_cursor[r], 1);
        g_adj[pos] = c;
    }
}

// ---------------------------------------------------------------------------
// 5) tensor-core GEMM: xl = x @ W + b ; y = dinv * xl stored fp16.
//    3xTF32 split (ahi*bhi + ahi*blo + alo*bhi) => ~fp32 accuracy.
//    Block: 256 thr, tile M=128 x N=64, K=128 resident.
//    Warp: 32x32 (2 m16-tiles x 4 n8-tiles). grid = 391*2.

#define XS_STRIDE 132   // floats; conflict-free A-frag LDS
#define WS_STRIDE 72    // floats; conflict-free B-frag LDS
#define SMEM_GEMM_BYTES ((128 * XS_STRIDE + 2 * 128 * WS_STRIDE) * 4)

__device__ __forceinline__ unsigned tf32_rna(float f) {
    unsigned r;
    asm("cvt.rna.tf32.f32 %0, %1;" : "=r"(r) : "f"(f));
    return r;
}

__device__ __forceinline__ void mma_tf32(float* c, const unsigned* a,
                                         unsigned b0, unsigned b1) {
    asm volatile(
        "mma.sync.aligned.m16n8k8.row.col.f32.tf32.tf32.f32 "
        "{%0,%1,%2,%3}, {%4,%5,%6,%7}, {%8,%9}, {%0,%1,%2,%3};"
        : "+f"(c[0]), "+f"(c[1]), "+f"(c[2]), "+f"(c[3])
        : "r"(a[0]), "r"(a[1]), "r"(a[2]), "r"(a[3]), "r"(b0), "r"(b1));
}

__global__ __launch_bounds__(256) void k_gemm(const float* __restrict__ x,
                                              const float* __restrict__ Wm,
                                              const float* __restrict__ bias,
                                              int n) {
    extern __shared__ float smem[];
    float* x_s  = smem;                       // [128][XS_STRIDE]
    float* w_hi = smem + 128 * XS_STRIDE;     // [128][WS_STRIDE]
    float* w_lo = w_hi + 128 * WS_STRIDE;     // [128][WS_STRIDE]

    const int tid   = threadIdx.x;
    const int lane  = tid & 31;
    const int wid   = tid >> 5;
    const int g     = lane >> 2;     // group id 0..7
    const int tig   = lane & 3;      // thread in group 0..3
    const int wm    = wid & 3;       // warp m-group (rows wm*32..+31)
    const int wn    = wid >> 2;      // warp n-group (cols wn*32..+31 of 64)
    const int m     = blockIdx.x >> 1;
    const int nhalf = blockIdx.x & 1;
    const int row0  = m * 128;
    const int ncol0 = nhalf * 64;

    // load x tile [128 rows][128 k] -> x_s (zero-padded rows)
    for (int i = tid; i < 128 * 32; i += 256) {
        int r = i >> 5, c4 = i & 31;
        float4 v = make_float4(0.f, 0.f, 0.f, 0.f);
        if (row0 + r < n) v = ((const float4*)x)[(size_t)(row0 + r) * 32 + c4];
        ((float4*)(x_s + r * XS_STRIDE))[c4] = v;
    }
    // load + split W cols [ncol0, ncol0+64)
    for (int i = tid; i < 128 * 16; i += 256) {
        int k = i >> 4, c4 = i & 15;
        float4 v = ((const float4*)(Wm + (size_t)k * D + ncol0))[c4];
        float4 hi, lo;
        hi.x = __uint_as_float(tf32_rna(v.x)); lo.x = v.x - hi.x;
        hi.y = __uint_as_float(tf32_rna(v.y)); lo.y = v.y - hi.y;
        hi.z = __uint_as_float(tf32_rna(v.z)); lo.z = v.z - hi.z;
        hi.w = __uint_as_float(tf32_rna(v.w)); lo.w = v.w - hi.w;
        ((float4*)(w_hi + k * WS_STRIDE))[c4] = hi;
        ((float4*)(w_lo + k * WS_STRIDE))[c4] = lo;
    }
    __syncthreads();

    const unsigned* wh_u = (const unsigned*)w_hi;
    const unsigned* wl_u = (const unsigned*)w_lo;

    float acc[2][4][4];
#pragma unroll
    for (int mt = 0; mt < 2; mt++)
#pragma unroll
        for (int j = 0; j < 4; j++)
#pragma unroll
            for (int q = 0; q < 4; q++) acc[mt][j][q] = 0.0f;

#pragma unroll 4
    for (int s = 0; s < 16; s++) {
        const int k0 = s * 8;
        unsigned ahi[2][4], alo[2][4];
#pragma unroll
        for (int mt = 0; mt < 2; mt++) {
            const int rb = wm * 32 + mt * 16;
            float av[4];
            av[0] = x_s[(rb + g)     * XS_STRIDE + k0 + tig];
            av[1] = x_s[(rb + g + 8) * XS_STRIDE + k0 + tig];
            av[2] = x_s[(rb + g)     * XS_STRIDE + k0 + tig + 4];
            av[3] = x_s[(rb + g + 8) * XS_STRIDE + k0 + tig + 4];
#pragma unroll
            for (int q = 0; q < 4; q++) {
                ahi[mt][q] = tf32_rna(av[q]);
                alo[mt][q] = __float_as_uint(av[q] - __uint_as_float(ahi[mt][q]));
            }
        }
#pragma unroll
        for (int j = 0; j < 4; j++) {
            const int nb = wn * 32 + 8 * j + g;
            unsigned bhi0 = wh_u[(k0 + tig)     * WS_STRIDE + nb];
            unsigned bhi1 = wh_u[(k0 + tig + 4) * WS_STRIDE + nb];
            unsigned blo0 = wl_u[(k0 + tig)     * WS_STRIDE + nb];
            unsigned blo1 = wl_u[(k0 + tig + 4) * WS_STRIDE + nb];
#pragma unroll
            for (int mt = 0; mt < 2; mt++) {
                mma_tf32(acc[mt][j], ahi[mt], bhi0, bhi1);
                mma_tf32(acc[mt][j], ahi[mt], blo0, blo1);
                mma_tf32(acc[mt][j], alo[mt], bhi0, bhi1);
            }
        }
    }

    // epilogue: +bias, *dinv, fp16 pack -> g_yh (half2 index: row*64 + hcol)
    unsigned* yh_u = (unsigned*)g_yh;
#pragma unroll
    for (int mt = 0; mt < 2; mt++) {
        const int rA = row0 + wm * 32 + mt * 16 + g;
        const int rB = rA + 8;
        const float dA = (rA < n) ? g_dinv[rA] : 0.f;
        const float dB = (rB < n) ? g_dinv[rB] : 0.f;
#pragma unroll
        for (int j = 0; j < 4; j++) {
            const int hcol = (ncol0 + wn * 32 + 8 * j) / 2 + tig;  // half2 col
            const float2 bp = ((const float2*)bias)[hcol];
            if (rA < n) {
                __half2 h = __floats2half2_rn((acc[mt][j][0] + bp.x) * dA,
                                              (acc[mt][j][1] + bp.y) * dA);
                yh_u[(size_t)rA * 64 + hcol] = *(unsigned*)&h;
            }
            if (rB < n) {
                __half2 h = __floats2half2_rn((acc[mt][j][2] + bp.x) * dB,
                                              (acc[mt][j][3] + bp.y) * dB);
                yh_u[(size_t)rB * 64 + hcol] = *(unsigned*)&h;
            }
        }
    }
}

// ---------------------------------------------------------------------------
// 6) gather: one warp per node, fp16 loads, fp32 register accumulation.
//    out[r] = dinv[r] * ( y[r] + sum_{c in adj[r]} y[c] )
__global__ __launch_bounds__(256) void k_gather(float* __restrict__ out, int n) {
    const int node = blockIdx.x * 8 + (threadIdx.x >> 5);
    const int lane = threadIdx.x & 31;
    if (node >= n) return;

    const uint2* __restrict__ y2 = (const uint2*)g_yh;  // node*32 + lane

    float4 a0, a1 = make_float4(0.f, 0.f, 0.f, 0.f);
    {   // self-loop term
        uint2 u = y2[(size_t)node * 32 + lane];
        float2 f0 = __half22float2(*(__half2*)&u.x);
        float2 f1 = __half22float2(*(__half2*)&u.y);
        a0 = make_float4(f0.x, f0.y, f1.x, f1.y);
    }

    const int s = g_roff[node];
    const int e = g_roff[node + 1];

    for (int j = s; j < e; j += 32) {
        int cid = 0;
        if (j + lane < e) cid = g_adj[j + lane];
        const int cnt = min(32, e - j);
        int t = 0;
        for (; t + 4 <= cnt; t += 4) {
            int c0 = __shfl_sync(0xffffffffu, cid, t + 0);
            int c1 = __shfl_sync(0xffffffffu, cid, t + 1);
            int c2 = __shfl_sync(0xffffffffu, cid, t + 2);
            int c3 = __shfl_sync(0xffffffffu, cid, t + 3);
            uint2 u0 = y2[(size_t)c0 * 32 + lane];
            uint2 u1 = y2[(size_t)c1 * 32 + lane];
            uint2 u2 = y2[(size_t)c2 * 32 + lane];
            uint2 u3 = y2[(size_t)c3 * 32 + lane];
            float2 f;
            f = __half22float2(*(__half2*)&u0.x); a0.x += f.x; a0.y += f.y;
            f = __half22float2(*(__half2*)&u0.y); a0.z += f.x; a0.w += f.y;
            f = __half22float2(*(__half2*)&u1.x); a1.x += f.x; a1.y += f.y;
            f = __half22float2(*(__half2*)&u1.y); a1.z += f.x; a1.w += f.y;
            f = __half22float2(*(__half2*)&u2.x); a0.x += f.x; a0.y += f.y;
            f = __half22float2(*(__half2*)&u2.y); a0.z += f.x; a0.w += f.y;
            f = __half22float2(*(__half2*)&u3.x); a1.x += f.x; a1.y += f.y;
            f = __half22float2(*(__half2*)&u3.y); a1.z += f.x; a1.w += f.y;
        }
        for (; t < cnt; t++) {
            int c = __shfl_sync(0xffffffffu, cid, t);
            uint2 u = y2[(size_t)c * 32 + lane];
            float2 f;
            f = __half22float2(*(__half2*)&u.x); a0.x += f.x; a0.y += f.y;
            f = __half22float2(*(__half2*)&u.y); a0.z += f.x; a0.w += f.y;
        }
    }

    const float sd = g_dinv[node];
    float4 r;
    r.x = (a0.x + a1.x) * sd;
    r.y = (a0.y + a1.y) * sd;
    r.z = (a0.z + a1.z) * sd;
    r.w = (a0.w + a1.w) * sd;
    ((float4*)out)[(size_t)node * 32 + lane] = r;
}

// ---------------------------------------------------------------------------
extern "C" void kernel_launch(void* const* d_in, const int* in_sizes, int n_in,
                              void* d_out, int out_size) {
    const float* x  = (const float*)d_in[0];
    const int*   ei = (const int*)d_in[1];    // int32 (JAX canonicalized)
    const float* Wm = (const float*)d_in[2];
    const float* b  = (const float*)d_in[3];
    float* out = (float*)d_out;

    const int n = in_sizes[0] / D;       // 50000
    const int E = in_sizes[1] / 2;       // 1,600,000

    const int nb = (n + 1023) / 1024;    // 49 scan blocks
    const int mtiles = (n + 127) / 128;  // 391

    cudaFuncSetAttribute(k_gemm, cudaFuncAttributeMaxDynamicSharedMemorySize,
                         SMEM_GEMM_BYTES);

    k_init    <<<(n + 255) / 256, 256>>>(n);
    k_hist    <<<(E + 255) / 256, 256>>>(ei, E);
    k_scan_blk<<<nb, 1024>>>(n);
    k_scan_top<<<1, 64>>>(nb, n);
    k_scan_add<<<(n + 255) / 256, 256>>>(n);
    k_fill    <<<(E + 255) / 256, 256>>>(ei, E);
    k_gemm    <<<mtiles * 2, 256, SMEM_GEMM_BYTES>>>(x, Wm, b, n);
    k_gather  <<<(n + 7) / 8, 256>>>(out, n);
}

// round 13
// speedup vs baseline: 1.1379x; 1.1379x over previous
#include <cuda_runtime.h>
#include <cuda_fp16.h>
#include <cstdint>

#define D 128
#define N_MAX 50048
#define E_MAX 1600512
#define NB_MAX 64   // scan blocks (ceil(50000/1024)=49), all co-resident

// Scratch (device globals: allocation-free per harness rules)
__device__ int              g_deg[N_MAX];
__device__ int              g_rowcnt[N_MAX];
__device__ int              g_roff[N_MAX + 1];
__device__ int              g_cursor[N_MAX];
__device__ unsigned int     g_scst[NB_MAX];   // lookback: (state<<30)|sum
__device__ int              g_adj[E_MAX];
__device__ float            g_dinv[N_MAX];
__device__ __half2          g_yh[(size_t)N_MAX * (D / 2)];  // fp16 y

// ---------------------------------------------------------------------------
// 1) init: self-loop degree 1, row counters 0, scan status invalid
__global__ void k_init(int n, int nb) {
    int i = blockIdx.x * blockDim.x + threadIdx.x;
    if (i < n) { g_deg[i] = 1; g_rowcnt[i] = 0; }
    if (i < nb) g_scst[i] = 0u;
}

// 2) fused histogram: degree over col, CSR counts over row (one pass over ei)
__global__ void k_hist(const int* __restrict__ ei, int E) {
    int i = blockIdx.x * blockDim.x + threadIdx.x;
    if (i < E) {
        int r = ei[i];
        int c = ei[E + i];
        atomicAdd(&g_deg[c], 1);
        atomicAdd(&g_rowcnt[r], 1);
    }
}

// ---------------------------------------------------------------------------
// 3) single-pass decoupled-lookback scan of rowcnt -> roff/cursor, + dinv.
//    49 blocks <= 148 SMs: all co-resident, lookback cannot deadlock.
//    Status word: bits[31:30] = {0:invalid, 1:aggregate, 2:prefix}, bits[29:0]=sum.
__global__ __launch_bounds__(1024) void k_scan(int n, int nb) {
    __shared__ int warp_sums[32];
    __shared__ int s_prefix;
    const int tid = threadIdx.x, lane = tid & 31, wid = tid >> 5;
    const int bid = blockIdx.x;
    const int i = bid * 1024 + tid;

    int v = (i < n) ? g_rowcnt[i] : 0;
    int inc = v;
#pragma unroll
    for (int o = 1; o < 32; o <<= 1) {
        int t = __shfl_up_sync(0xffffffffu, inc, o);
        if (lane >= o) inc += t;
    }
    if (lane == 31) warp_sums[wid] = inc;
    __syncthreads();
    if (wid == 0) {
        int ws = warp_sums[lane];
#pragma unroll
        for (int o = 1; o < 32; o <<= 1) {
            int t = __shfl_up_sync(0xffffffffu, ws, o);
            if (lane >= o) ws += t;
        }
        warp_sums[lane] = ws;
    }
    __syncthreads();
    const int block_total = warp_sums[31];
    const int local_excl  = ((wid == 0) ? 0 : warp_sums[wid - 1]) + inc - v;

    if (tid == 0) {
        if (bid == 0) {
            atomicExch(&g_scst[0], (2u << 30) | (unsigned)block_total);
            s_prefix = 0;
        } else {
            // publish aggregate, then look back
            atomicExch(&g_scst[bid], (1u << 30) | (unsigned)block_total);
            int pre = 0;
            int j = bid - 1;
            while (true) {
                unsigned st = atomicAdd(&g_scst[j], 0u);  // strong read
                unsigned tag = st >> 30;
                if (tag == 0u) continue;          // not yet published
                pre += (int)(st & 0x3fffffffu);
                if (tag == 2u) break;             // hit a full prefix
                j--;
            }
            s_prefix = pre;
            atomicExch(&g_scst[bid],
                       (2u << 30) | (unsigned)(pre + block_total));
        }
    }
    __syncthreads();

    if (i < n) {
        int r = s_prefix + local_excl;
        g_roff[i]   = r;
        g_cursor[i] = r;
        g_dinv[i]   = rsqrtf((float)g_deg[i]);
    }
    if (bid == nb - 1 && tid == 0) g_roff[n] = s_prefix + block_total;
}

// 4) CSR fill: adj[cursor[r]++] = c  (order within a row irrelevant: sum)
__global__ void k_fill(const int* __restrict__ ei, int E) {
    int i = blockIdx.x * blockDim.x + threadIdx.x;
    if (i < E) {
        int r = ei[i];
        int c = ei[E + i];
        int pos = atomicAdd(&g_cursor[r], 1);
        g_adj[pos] = c;
    }
}

// ---------------------------------------------------------------------------
// 5) xl = x @ W + b ; y = dinv * xl stored as fp16. BM=64, BN=128, BK=64.
//    fp32 FFMA version: measured 49.8us ~ 97% of FFMA roofline.
__global__ __launch_bounds__(256) void k_gemm(const float* __restrict__ x,
                                              const float* __restrict__ Wm,
                                              const float* __restrict__ bias,
                                              int n) {
    __shared__ float w_s[64][D];   // 32 KB
    __shared__ float x_s[64][64];  // 16 KB

    const int tid  = threadIdx.x;
    const int tx   = tid & 31;     // col quad
    const int ty   = tid >> 5;     // row group
    const int row0 = blockIdx.x * 64;

    float acc[8][4];
#pragma unroll
    for (int i = 0; i < 8; i++)
#pragma unroll
        for (int j = 0; j < 4; j++) acc[i][j] = 0.0f;

    for (int kk = 0; kk < D; kk += 64) {
        {
            const float4* W4 = (const float4*)(Wm + (size_t)kk * D);
            float4* ws4 = (float4*)&w_s[0][0];
            for (int i = tid; i < 64 * (D / 4); i += 256) ws4[i] = W4[i];
        }
        {
            for (int i = tid; i < 64 * 16; i += 256) {
                int r = i >> 4, c4 = i & 15;
                float4 v = make_float4(0.f, 0.f, 0.f, 0.f);
                if (row0 + r < n)
                    v = *(const float4*)(x + (size_t)(row0 + r) * D + kk + c4 * 4);
                *(float4*)&x_s[r][c4 * 4] = v;
            }
        }
        __syncthreads();

#pragma unroll 4
        for (int k = 0; k < 64; k++) {
            float4 wv = ((const float4*)&w_s[k][0])[tx];
#pragma unroll
            for (int i = 0; i < 8; i++) {
                float xv = x_s[ty * 8 + i][k];
                acc[i][0] += xv * wv.x;
                acc[i][1] += xv * wv.y;
                acc[i][2] += xv * wv.z;
                acc[i][3] += xv * wv.w;
            }
        }
        __syncthreads();
    }

    float4 bv = ((const float4*)bias)[tx];
#pragma unroll
    for (int i = 0; i < 8; i++) {
        int row = row0 + ty * 8 + i;
        if (row < n) {
            float s = g_dinv[row];
            __half2 h0 = __floats2half2_rn((acc[i][0] + bv.x) * s,
                                           (acc[i][1] + bv.y) * s);
            __half2 h1 = __floats2half2_rn((acc[i][2] + bv.z) * s,
                                           (acc[i][3] + bv.w) * s);
            uint2 u;
            u.x = *(unsigned int*)&h0;
            u.y = *(unsigned int*)&h1;
            ((uint2*)g_yh)[(size_t)row * 32 + tx] = u;
        }
    }
}

// ---------------------------------------------------------------------------
// 6) gather: one warp per node, fp16 loads, fp32 register accumulation.
//    out[r] = dinv[r] * ( y[r] + sum_{c in adj[r]} y[c] )
__global__ __launch_bounds__(256) void k_gather(float* __restrict__ out, int n) {
    const int node = blockIdx.x * 8 + (threadIdx.x >> 5);
    const int lane = threadIdx.x & 31;
    if (node >= n) return;

    const uint2* __restrict__ y2 = (const uint2*)g_yh;  // node*32 + lane

    float4 a0, a1 = make_float4(0.f, 0.f, 0.f, 0.f);
    {   // self-loop term
        uint2 u = y2[(size_t)node * 32 + lane];
        float2 f0 = __half22float2(*(__half2*)&u.x);
        float2 f1 = __half22float2(*(__half2*)&u.y);
        a0 = make_float4(f0.x, f0.y, f1.x, f1.y);
    }

    const int s = g_roff[node];
    const int e = g_roff[node + 1];

    for (int j = s; j < e; j += 32) {
        int cid = 0;
        if (j + lane < e) cid = g_adj[j + lane];
        const int cnt = min(32, e - j);
        int t = 0;
        for (; t + 4 <= cnt; t += 4) {
            int c0 = __shfl_sync(0xffffffffu, cid, t + 0);
            int c1 = __shfl_sync(0xffffffffu, cid, t + 1);
            int c2 = __shfl_sync(0xffffffffu, cid, t + 2);
            int c3 = __shfl_sync(0xffffffffu, cid, t + 3);
            uint2 u0 = y2[(size_t)c0 * 32 + lane];
            uint2 u1 = y2[(size_t)c1 * 32 + lane];
            uint2 u2 = y2[(size_t)c2 * 32 + lane];
            uint2 u3 = y2[(size_t)c3 * 32 + lane];
            float2 f;
            f = __half22float2(*(__half2*)&u0.x); a0.x += f.x; a0.y += f.y;
            f = __half22float2(*(__half2*)&u0.y); a0.z += f.x; a0.w += f.y;
            f = __half22float2(*(__half2*)&u1.x); a1.x += f.x; a1.y += f.y;
            f = __half22float2(*(__half2*)&u1.y); a1.z += f.x; a1.w += f.y;
            f = __half22float2(*(__half2*)&u2.x); a0.x += f.x; a0.y += f.y;
            f = __half22float2(*(__half2*)&u2.y); a0.z += f.x; a0.w += f.y;
            f = __half22float2(*(__half2*)&u3.x); a1.x += f.x; a1.y += f.y;
            f = __half22float2(*(__half2*)&u3.y); a1.z += f.x; a1.w += f.y;
        }
        for (; t < cnt; t++) {
            int c = __shfl_sync(0xffffffffu, cid, t);
            uint2 u = y2[(size_t)c * 32 + lane];
            float2 f;
            f = __half22float2(*(__half2*)&u.x); a0.x += f.x; a0.y += f.y;
            f = __half22float2(*(__half2*)&u.y); a0.z += f.x; a0.w += f.y;
        }
    }

    const float sd = g_dinv[node];
    float4 r;
    r.x = (a0.x + a1.x) * sd;
    r.y = (a0.y + a1.y) * sd;
    r.z = (a0.z + a1.z) * sd;
    r.w = (a0.w + a1.w) * sd;
    ((float4*)out)[(size_t)node * 32 + lane] = r;
}

// ---------------------------------------------------------------------------
extern "C" void kernel_launch(void* const* d_in, const int* in_sizes, int n_in,
                              void* d_out, int out_size) {
    const float* x  = (const float*)d_in[0];
    const int*   ei = (const int*)d_in[1];    // int32 (JAX canonicalized)
    const float* Wm = (const float*)d_in[2];
    const float* b  = (const float*)d_in[3];
    float* out = (float*)d_out;

    const int n = in_sizes[0] / D;       // 50000
    const int E = in_sizes[1] / 2;       // 1,600,000

    const int nb = (n + 1023) / 1024;    // 49 scan blocks (<= 148 SMs)

    k_init  <<<(n + 255) / 256, 256>>>(n, nb);
    k_hist  <<<(E + 255) / 256, 256>>>(ei, E);
    k_scan  <<<nb, 1024>>>(n, nb);
    k_fill  <<<(E + 255) / 256, 256>>>(ei, E);
    k_gemm  <<<(n + 63) / 64, 256>>>(x, Wm, b, n);
    k_gather<<<(n + 7) / 8, 256>>>(out, n);
}

// round 14
// speedup vs baseline: 1.1590x; 1.0185x over previous
#include <cuda_runtime.h>
#include <cuda_fp16.h>
#include <cstdint>

#define D 128
#define N_MAX 50048
#define E_MAX 1600512
#define NB_MAX 64   // max scan blocks (ceil(50000/1024)=49)

// Scratch (device globals: allocation-free per harness rules)
__device__ int     g_deg[N_MAX];
__device__ int     g_rowcnt[N_MAX];
__device__ int     g_roff[N_MAX + 1];
__device__ int     g_cursor[N_MAX];
__device__ int     g_bsum[NB_MAX];
__device__ int     g_boff[NB_MAX];
__device__ int     g_adj[E_MAX];
__device__ float   g_dinv[N_MAX];
__device__ __half2 g_yh[(size_t)N_MAX * (D / 2)];  // y in fp16

// ---------------------------------------------------------------------------
// 1) init: self-loop degree 1, row counters 0
__global__ void k_init(int n) {
    int i = blockIdx.x * blockDim.x + threadIdx.x;
    if (i < n) { g_deg[i] = 1; g_rowcnt[i] = 0; }
}

// 2) fused histogram, 4 edges per thread (MLP=4 on the REDs/LDGs)
__global__ void k_hist(const int* __restrict__ ei, int E, int T) {
    int i = blockIdx.x * blockDim.x + threadIdx.x;
    if (i >= T) return;
#pragma unroll
    for (int j = 0; j < 4; j++) {
        int e = i + j * T;
        if (e < E) {
            int r = __ldg(ei + e);
            int c = __ldg(ei + E + e);
            atomicAdd(&g_deg[c], 1);       // no return use -> REDG
            atomicAdd(&g_rowcnt[r], 1);
        }
    }
}

// ---------------------------------------------------------------------------
// 3a) per-block exclusive scan of 1024-element chunks + block sums
__global__ __launch_bounds__(1024) void k_scan_blk(int n) {
    __shared__ int warp_sums[32];
    const int tid = threadIdx.x, lane = tid & 31, wid = tid >> 5;
    const int i = blockIdx.x * 1024 + tid;

    int v = (i < n) ? g_rowcnt[i] : 0;
    int inc = v;
#pragma unroll
    for (int o = 1; o < 32; o <<= 1) {
        int t = __shfl_up_sync(0xffffffffu, inc, o);
        if (lane >= o) inc += t;
    }
    if (lane == 31) warp_sums[wid] = inc;
    __syncthreads();
    if (wid == 0) {
        int ws = warp_sums[lane];
#pragma unroll
        for (int o = 1; o < 32; o <<= 1) {
            int t = __shfl_up_sync(0xffffffffu, ws, o);
            if (lane >= o) ws += t;
        }
        warp_sums[lane] = ws;
    }
    __syncthreads();
    int excl = ((wid == 0) ? 0 : warp_sums[wid - 1]) + inc - v;
    if (i < n) g_roff[i] = excl;
    if (tid == 0) g_bsum[blockIdx.x] = warp_sums[31];
}

// 3b) scan the block sums (nb <= 64, one 64-thread block)
__global__ void k_scan_top(int nb, int n) {
    __shared__ int ws[2];
    const int tid = threadIdx.x, lane = tid & 31, wid = tid >> 5;
    int v = (tid < nb) ? g_bsum[tid] : 0;
    int inc = v;
#pragma unroll
    for (int o = 1; o < 32; o <<= 1) {
        int t = __shfl_up_sync(0xffffffffu, inc, o);
        if (lane >= o) inc += t;
    }
    if (lane == 31) ws[wid] = inc;
    __syncthreads();
    int excl = inc - v + ((wid == 1) ? ws[0] : 0);
    if (tid < nb) g_boff[tid] = excl;
    if (tid == nb - 1) g_roff[n] = excl + v;
}

// 3c) add block offsets -> final roff/cursor; fused dinv = rsqrt(deg)
__global__ void k_scan_add(int n) {
    int i = blockIdx.x * blockDim.x + threadIdx.x;
    if (i < n) {
        int r = g_roff[i] + g_boff[i >> 10];
        g_roff[i] = r;
        g_cursor[i] = r;
        g_dinv[i] = rsqrtf((float)g_deg[i]);
    }
}

// 4) CSR fill, 4 edges per thread: 4 independent ATOMG in flight (MLP=4)
__global__ void k_fill(const int* __restrict__ ei, int E, int T) {
    int i = blockIdx.x * blockDim.x + threadIdx.x;
    if (i >= T) return;
    int r[4], c[4], pos[4];
    bool ok[4];
#pragma unroll
    for (int j = 0; j < 4; j++) {
        int e = i + j * T;
        ok[j] = (e < E);
        if (ok[j]) {
            r[j] = __ldg(ei + e);
            c[j] = __ldg(ei + E + e);
        }
    }
#pragma unroll
    for (int j = 0; j < 4; j++)
        if (ok[j]) pos[j] = atomicAdd(&g_cursor[r[j]], 1);
#pragma unroll
    for (int j = 0; j < 4; j++)
        if (ok[j]) g_adj[pos[j]] = c[j];
}

// ---------------------------------------------------------------------------
// 5) xl = x @ W + b ; y = dinv * xl stored as fp16. BM=64, BN=128, BK=64.
//    fp32 FFMA version: measured 49.8us ~ 97% of FFMA roofline.
__global__ __launch_bounds__(256) void k_gemm(const float* __restrict__ x,
                                              const float* __restrict__ Wm,
                                              const float* __restrict__ bias,
                                              int n) {
    __shared__ float w_s[64][D];   // 32 KB
    __shared__ float x_s[64][64];  // 16 KB

    const int tid  = threadIdx.x;
    const int tx   = tid & 31;     // col quad
    const int ty   = tid >> 5;     // row group
    const int row0 = blockIdx.x * 64;

    float acc[8][4];
#pragma unroll
    for (int i = 0; i < 8; i++)
#pragma unroll
        for (int j = 0; j < 4; j++) acc[i][j] = 0.0f;

    for (int kk = 0; kk < D; kk += 64) {
        {
            const float4* W4 = (const float4*)(Wm + (size_t)kk * D);
            float4* ws4 = (float4*)&w_s[0][0];
            for (int i = tid; i < 64 * (D / 4); i += 256) ws4[i] = W4[i];
        }
        {
            for (int i = tid; i < 64 * 16; i += 256) {
                int r = i >> 4, c4 = i & 15;
                float4 v = make_float4(0.f, 0.f, 0.f, 0.f);
                if (row0 + r < n)
                    v = *(const float4*)(x + (size_t)(row0 + r) * D + kk + c4 * 4);
                *(float4*)&x_s[r][c4 * 4] = v;
            }
        }
        __syncthreads();

#pragma unroll 4
        for (int k = 0; k < 64; k++) {
            float4 wv = ((const float4*)&w_s[k][0])[tx];
#pragma unroll
            for (int i = 0; i < 8; i++) {
                float xv = x_s[ty * 8 + i][k];
                acc[i][0] += xv * wv.x;
                acc[i][1] += xv * wv.y;
                acc[i][2] += xv * wv.z;
                acc[i][3] += xv * wv.w;
            }
        }
        __syncthreads();
    }

    float4 bv = ((const float4*)bias)[tx];
#pragma unroll
    for (int i = 0; i < 8; i++) {
        int row = row0 + ty * 8 + i;
        if (row < n) {
            float s = g_dinv[row];
            __half2 h0 = __floats2half2_rn((acc[i][0] + bv.x) * s,
                                           (acc[i][1] + bv.y) * s);
            __half2 h1 = __floats2half2_rn((acc[i][2] + bv.z) * s,
                                           (acc[i][3] + bv.w) * s);
            uint2 u;
            u.x = *(unsigned int*)&h0;
            u.y = *(unsigned int*)&h1;
            ((uint2*)g_yh)[(size_t)row * 32 + tx] = u;
        }
    }
}

// ---------------------------------------------------------------------------
// 6) gather: one warp per node, fp16 loads, fp32 register accumulation.
//    out[r] = dinv[r] * ( y[r] + sum_{c in adj[r]} y[c] )
__global__ __launch_bounds__(256) void k_gather(float* __restrict__ out, int n) {
    const int node = blockIdx.x * 8 + (threadIdx.x >> 5);
    const int lane = threadIdx.x & 31;
    if (node >= n) return;

    const uint2* __restrict__ y2 = (const uint2*)g_yh;  // node*32 + lane

    float4 a0, a1 = make_float4(0.f, 0.f, 0.f, 0.f);
    {   // self-loop term
        uint2 u = y2[(size_t)node * 32 + lane];
        float2 f0 = __half22float2(*(__half2*)&u.x);
        float2 f1 = __half22float2(*(__half2*)&u.y);
        a0 = make_float4(f0.x, f0.y, f1.x, f1.y);
    }

    const int s = g_roff[node];
    const int e = g_roff[node + 1];

    for (int j = s; j < e; j += 32) {
        int cid = 0;
        if (j + lane < e) cid = g_adj[j + lane];
        const int cnt = min(32, e - j);
        int t = 0;
        for (; t + 4 <= cnt; t += 4) {
            int c0 = __shfl_sync(0xffffffffu, cid, t + 0);
            int c1 = __shfl_sync(0xffffffffu, cid, t + 1);
            int c2 = __shfl_sync(0xffffffffu, cid, t + 2);
            int c3 = __shfl_sync(0xffffffffu, cid, t + 3);
            uint2 u0 = y2[(size_t)c0 * 32 + lane];
            uint2 u1 = y2[(size_t)c1 * 32 + lane];
            uint2 u2 = y2[(size_t)c2 * 32 + lane];
            uint2 u3 = y2[(size_t)c3 * 32 + lane];
            float2 f;
            f = __half22float2(*(__half2*)&u0.x); a0.x += f.x; a0.y += f.y;
            f = __half22float2(*(__half2*)&u0.y); a0.z += f.x; a0.w += f.y;
            f = __half22float2(*(__half2*)&u1.x); a1.x += f.x; a1.y += f.y;
            f = __half22float2(*(__half2*)&u1.y); a1.z += f.x; a1.w += f.y;
            f = __half22float2(*(__half2*)&u2.x); a0.x += f.x; a0.y += f.y;
            f = __half22float2(*(__half2*)&u2.y); a0.z += f.x; a0.w += f.y;
            f = __half22float2(*(__half2*)&u3.x); a1.x += f.x; a1.y += f.y;
            f = __half22float2(*(__half2*)&u3.y); a1.z += f.x; a1.w += f.y;
        }
        for (; t < cnt; t++) {
            int c = __shfl_sync(0xffffffffu, cid, t);
            uint2 u = y2[(size_t)c * 32 + lane];
            float2 f;
            f = __half22float2(*(__half2*)&u.x); a0.x += f.x; a0.y += f.y;
            f = __half22float2(*(__half2*)&u.y); a0.z += f.x; a0.w += f.y;
        }
    }

    const float sd = g_dinv[node];
    float4 r;
    r.x = (a0.x + a1.x) * sd;
    r.y = (a0.y + a1.y) * sd;
    r.z = (a0.z + a1.z) * sd;
    r.w = (a0.w + a1.w) * sd;
    ((float4*)out)[(size_t)node * 32 + lane] = r;
}

// ---------------------------------------------------------------------------
extern "C" void kernel_launch(void* const* d_in, const int* in_sizes, int n_in,
                              void* d_out, int out_size) {
    const float* x  = (const float*)d_in[0];
    const int*   ei = (const int*)d_in[1];    // int32 (JAX canonicalized)
    const float* Wm = (const float*)d_in[2];
    const float* b  = (const float*)d_in[3];
    float* out = (float*)d_out;

    const int n = in_sizes[0] / D;       // 50000
    const int E = in_sizes[1] / 2;       // 1,600,000

    const int nb = (n + 1023) / 1024;    // 49 scan blocks
    const int T  = (E + 3) / 4;          // threads for 4-edge ILP kernels

    k_init    <<<(n + 255) / 256, 256>>>(n);
    k_hist    <<<(T + 255) / 256, 256>>>(ei, E, T);
    k_scan_blk<<<nb, 1024>>>(n);
    k_scan_top<<<1, 64>>>(nb, n);
    k_scan_add<<<(n + 255) / 256, 256>>>(n);
    k_fill    <<<(T + 255) / 256, 256>>>(ei, E, T);
    k_gemm    <<<(n + 63) / 64, 256>>>(x, Wm, b, n);
    k_gather  <<<(n + 7) / 8, 256>>>(out, n);
}

// round 16
// speedup vs baseline: 1.2139x; 1.0474x over previous
#include <cuda_runtime.h>
#include <cuda_fp16.h>
#include <cstdint>

#define D 128
#define N_MAX 50048
#define E_MAX 1600512
#define NB_MAX 64   // max scan blocks (ceil(50000/1024)=49)

// Scratch (device globals: allocation-free per harness rules)
__device__ int     g_deg[N_MAX];
__device__ int     g_rowcnt[N_MAX];
__device__ int     g_roff[N_MAX + 1];
__device__ int     g_cursor[N_MAX];
__device__ int     g_bsum[NB_MAX];
__device__ int     g_boff[NB_MAX];
__device__ int     g_adj[E_MAX];
__device__ float   g_dinv[N_MAX];
__device__ __half2 g_yh[(size_t)N_MAX * (D / 2)];  // y = xl (fp16, dinv NOT folded)

// ---------------------------------------------------------------------------
// 1) init: self-loop degree 1, row counters 0
__global__ void k_init(int n) {
    int i = blockIdx.x * blockDim.x + threadIdx.x;
    if (i < n) { g_deg[i] = 1; g_rowcnt[i] = 0; }
}

// 2) fused histogram: degree over col, CSR counts over row
__global__ void k_hist(const int* __restrict__ ei, int E) {
    int i = blockIdx.x * blockDim.x + threadIdx.x;
    if (i < E) {
        int r = ei[i];
        int c = ei[E + i];
        atomicAdd(&g_deg[c], 1);
        atomicAdd(&g_rowcnt[r], 1);
    }
}

// ---------------------------------------------------------------------------
// 3a) per-block exclusive scan of 1024-element chunks + block sums
__global__ __launch_bounds__(1024) void k_scan_blk(int n) {
    __shared__ int warp_sums[32];
    const int tid = threadIdx.x, lane = tid & 31, wid = tid >> 5;
    const int i = blockIdx.x * 1024 + tid;

    int v = (i < n) ? g_rowcnt[i] : 0;
    int inc = v;
#pragma unroll
    for (int o = 1; o < 32; o <<= 1) {
        int t = __shfl_up_sync(0xffffffffu, inc, o);
        if (lane >= o) inc += t;
    }
    if (lane == 31) warp_sums[wid] = inc;
    __syncthreads();
    if (wid == 0) {
        int ws = warp_sums[lane];
#pragma unroll
        for (int o = 1; o < 32; o <<= 1) {
            int t = __shfl_up_sync(0xffffffffu, ws, o);
            if (lane >= o) ws += t;
        }
        warp_sums[lane] = ws;
    }
    __syncthreads();
    int excl = ((wid == 0) ? 0 : warp_sums[wid - 1]) + inc - v;
    if (i < n) g_roff[i] = excl;
    if (tid == 0) g_bsum[blockIdx.x] = warp_sums[31];
}

// 3b) scan the block sums (nb <= 64, one 64-thread block)
__global__ void k_scan_top(int nb, int n) {
    __shared__ int ws[2];
    const int tid = threadIdx.x, lane = tid & 31, wid = tid >> 5;
    int v = (tid < nb) ? g_bsum[tid] : 0;
    int inc = v;
#pragma unroll
    for (int o = 1; o < 32; o <<= 1) {
        int t = __shfl_up_sync(0xffffffffu, inc, o);
        if (lane >= o) inc += t;
    }
    if (lane == 31) ws[wid] = inc;
    __syncthreads();
    int excl = inc - v + ((wid == 1) ? ws[0] : 0);
    if (tid < nb) g_boff[tid] = excl;
    if (tid == nb - 1) g_roff[n] = excl + v;
}

// 3c) add block offsets -> final roff/cursor; fused dinv = rsqrt(deg)
__global__ void k_scan_add(int n) {
    int i = blockIdx.x * blockDim.x + threadIdx.x;
    if (i < n) {
        int r = g_roff[i] + g_boff[i >> 10];
        g_roff[i] = r;
        g_cursor[i] = r;
        g_dinv[i] = rsqrtf((float)g_deg[i]);
    }
}

// 4) CSR fill: adj[cursor[r]++] = c
__global__ void k_fill(const int* __restrict__ ei, int E) {
    int i = blockIdx.x * blockDim.x + threadIdx.x;
    if (i < E) {
        int r = ei[i];
        int c = ei[E + i];
        int pos = atomicAdd(&g_cursor[r], 1);
        g_adj[pos] = c;
    }
}

// ---------------------------------------------------------------------------
// 5) xl = x @ W + b stored fp16 (no dinv -> independent of edge chain;
//    runs concurrently on side stream). BM=64, BN=128, BK=64 FFMA kernel
//    (measured ~97% of FFMA roofline).
__global__ __launch_bounds__(256) void k_gemm(const float* __restrict__ x,
                                              const float* __restrict__ Wm,
                                              const float* __restrict__ bias,
                                              int n) {
    __shared__ float w_s[64][D];   // 32 KB
    __shared__ float x_s[64][64];  // 16 KB

    const int tid  = threadIdx.x;
    const int tx   = tid & 31;     // col quad
    const int ty   = tid >> 5;     // row group
    const int row0 = blockIdx.x * 64;

    float acc[8][4];
#pragma unroll
    for (int i = 0; i < 8; i++)
#pragma unroll
        for (int j = 0; j < 4; j++) acc[i][j] = 0.0f;

    for (int kk = 0; kk < D; kk += 64) {
        {
            const float4* W4 = (const float4*)(Wm + (size_t)kk * D);
            float4* ws4 = (float4*)&w_s[0][0];
            for (int i = tid; i < 64 * (D / 4); i += 256) ws4[i] = W4[i];
        }
        {
            for (int i = tid; i < 64 * 16; i += 256) {
                int r = i >> 4, c4 = i & 15;
                float4 v = make_float4(0.f, 0.f, 0.f, 0.f);
                if (row0 + r < n)
                    v = *(const float4*)(x + (size_t)(row0 + r) * D + kk + c4 * 4);
                *(float4*)&x_s[r][c4 * 4] = v;
            }
        }
        __syncthreads();

#pragma unroll 4
        for (int k = 0; k < 64; k++) {
            float4 wv = ((const float4*)&w_s[k][0])[tx];
#pragma unroll
            for (int i = 0; i < 8; i++) {
                float xv = x_s[ty * 8 + i][k];
                acc[i][0] += xv * wv.x;
                acc[i][1] += xv * wv.y;
                acc[i][2] += xv * wv.z;
                acc[i][3] += xv * wv.w;
            }
        }
        __syncthreads();
    }

    float4 bv = ((const float4*)bias)[tx];
#pragma unroll
    for (int i = 0; i < 8; i++) {
        int row = row0 + ty * 8 + i;
        if (row < n) {
            __half2 h0 = __floats2half2_rn(acc[i][0] + bv.x, acc[i][1] + bv.y);
            __half2 h1 = __floats2half2_rn(acc[i][2] + bv.z, acc[i][3] + bv.w);
            uint2 u;
            u.x = *(unsigned int*)&h0;
            u.y = *(unsigned int*)&h1;
            ((uint2*)g_yh)[(size_t)row * 32 + tx] = u;
        }
    }
}

// ---------------------------------------------------------------------------
// 6) gather: one warp per node. dinv applied here:
//    out[r] = dinv[r] * ( dinv[r]*xl[r] + sum_c dinv[c]*xl[c] )
__global__ __launch_bounds__(256) void k_gather(float* __restrict__ out, int n) {
    const int node = blockIdx.x * 8 + (threadIdx.x >> 5);
    const int lane = threadIdx.x & 31;
    if (node >= n) return;

    const uint2* __restrict__ y2 = (const uint2*)g_yh;  // node*32 + lane
    const float sd = g_dinv[node];

    float4 a0, a1 = make_float4(0.f, 0.f, 0.f, 0.f);
    {   // self-loop term: dinv[r]*xl[r]
        uint2 u = y2[(size_t)node * 32 + lane];
        float2 f0 = __half22float2(*(__half2*)&u.x);
        float2 f1 = __half22float2(*(__half2*)&u.y);
        a0 = make_float4(sd * f0.x, sd * f0.y, sd * f1.x, sd * f1.y);
    }

    const int s = g_roff[node];
    const int e = g_roff[node + 1];

    for (int j = s; j < e; j += 32) {
        int cid = 0; float dv = 0.f;
        if (j + lane < e) {
            cid = g_adj[j + lane];
            dv  = g_dinv[cid];
        }
        const int cnt = min(32, e - j);
        int t = 0;
        for (; t + 4 <= cnt; t += 4) {
            int   c0 = __shfl_sync(0xffffffffu, cid, t + 0);
            float d0 = __shfl_sync(0xffffffffu, dv,  t + 0);
            int   c1 = __shfl_sync(0xffffffffu, cid, t + 1);
            float d1 = __shfl_sync(0xffffffffu, dv,  t + 1);
            int   c2 = __shfl_sync(0xffffffffu, cid, t + 2);
            float d2 = __shfl_sync(0xffffffffu, dv,  t + 2);
            int   c3 = __shfl_sync(0xffffffffu, cid, t + 3);
            float d3 = __shfl_sync(0xffffffffu, dv,  t + 3);
            uint2 u0 = y2[(size_t)c0 * 32 + lane];
            uint2 u1 = y2[(size_t)c1 * 32 + lane];
            uint2 u2 = y2[(size_t)c2 * 32 + lane];
            uint2 u3 = y2[(size_t)c3 * 32 + lane];
            float2 f;
            f = __half22float2(*(__half2*)&u0.x); a0.x += d0*f.x; a0.y += d0*f.y;
            f = __half22float2(*(__half2*)&u0.y); a0.z += d0*f.x; a0.w += d0*f.y;
            f = __half22float2(*(__half2*)&u1.x); a1.x += d1*f.x; a1.y += d1*f.y;
            f = __half22float2(*(__half2*)&u1.y); a1.z += d1*f.x; a1.w += d1*f.y;
            f = __half22float2(*(__half2*)&u2.x); a0.x += d2*f.x; a0.y += d2*f.y;
            f = __half22float2(*(__half2*)&u2.y); a0.z += d2*f.x; a0.w += d2*f.y;
            f = __half22float2(*(__half2*)&u3.x); a1.x += d3*f.x; a1.y += d3*f.y;
            f = __half22float2(*(__half2*)&u3.y); a1.z += d3*f.x; a1.w += d3*f.y;
        }
        for (; t < cnt; t++) {
            int   c = __shfl_sync(0xffffffffu, cid, t);
            float d = __shfl_sync(0xffffffffu, dv,  t);
            uint2 u = y2[(size_t)c * 32 + lane];
            float2 f;
            f = __half22float2(*(__half2*)&u.x); a0.x += d*f.x; a0.y += d*f.y;
            f = __half22float2(*(__half2*)&u.y); a0.z += d*f.x; a0.w += d*f.y;
        }
    }

    float4 r;
    r.x = (a0.x + a1.x) * sd;
    r.y = (a0.y + a1.y) * sd;
    r.z = (a0.z + a1.z) * sd;
    r.w = (a0.w + a1.w) * sd;
    ((float4*)out)[(size_t)node * 32 + lane] = r;
}

// ---------------------------------------------------------------------------
extern "C" void kernel_launch(void* const* d_in, const int* in_sizes, int n_in,
                              void* d_out, int out_size) {
    const float* x  = (const float*)d_in[0];
    const int*   ei = (const int*)d_in[1];    // int32 (JAX canonicalized)
    const float* Wm = (const float*)d_in[2];
    const float* b  = (const float*)d_in[3];
    float* out = (float*)d_out;

    const int n = in_sizes[0] / D;       // 50000
    const int E = in_sizes[1] / 2;       // 1,600,000

    const int nb = (n + 1023) / 1024;    // 49 scan blocks

    // One-time stream/event creation (thread-safe local static; happens on the
    // eager correctness call, OUTSIDE graph capture; identical launches every
    // call afterwards -> deterministic work). No device-memory allocation.
    struct Res {
        cudaStream_t s2;
        cudaEvent_t  ev_fork, ev_join;
        Res() {
            cudaStreamCreateWithFlags(&s2, cudaStreamNonBlocking);
            cudaEventCreateWithFlags(&ev_fork, cudaEventDisableTiming);
            cudaEventCreateWithFlags(&ev_join, cudaEventDisableTiming);
        }
    };
    static Res R;

    // --- Fork: side stream must be forked FROM the captured origin stream ---
    cudaEventRecord(R.ev_fork, 0);
    cudaStreamWaitEvent(R.s2, R.ev_fork, 0);

    // Side branch: GEMM (independent of edge chain).
    k_gemm<<<(n + 63) / 64, 256, 0, R.s2>>>(x, Wm, b, n);
    cudaEventRecord(R.ev_join, R.s2);

    // Main branch: CSR build + dinv.
    k_init    <<<(n + 255) / 256, 256>>>(n);
    k_hist    <<<(E + 255) / 256, 256>>>(ei, E);
    k_scan_blk<<<nb, 1024>>>(n);
    k_scan_top<<<1, 64>>>(nb, n);
    k_scan_add<<<(n + 255) / 256, 256>>>(n);
    k_fill    <<<(E + 255) / 256, 256>>>(ei, E);

    // Join: gather needs both y (side) and adj/roff/dinv (main).
    cudaStreamWaitEvent(0, R.ev_join, 0);
    k_gather  <<<(n + 7) / 8, 256>>>(out, n);
}